// round 1
// baseline (speedup 1.0000x reference)
#include <cuda_runtime.h>
#include <math.h>

#define MAXN 100000
#define NS 16
#define C 64
#define SP 8           // share planes
#define CS 8           // C / SP

// Scratch for Q/K/V projections (allocation-free rule: __device__ globals)
__device__ float g_q[MAXN * C];
__device__ float g_k[MAXN * C];
__device__ float g_v[MAXN * C];

// ---------------------------------------------------------------------------
// Kernel 1: QKV projection. grid = (ceil(N/64), 3). 256 threads.
// Computes out[r, c] = x[r, :] @ W[:, c] + b[c] for W in {Wq, Wk, Wv}.
// K = 64, so one smem tile pass. 4x4 register tiling per thread.
// ---------------------------------------------------------------------------
__global__ void __launch_bounds__(256) qkv_gemm(
    const float* __restrict__ x,
    const float* __restrict__ Wq, const float* __restrict__ bq,
    const float* __restrict__ Wk, const float* __restrict__ bk,
    const float* __restrict__ Wv, const float* __restrict__ bv,
    int N)
{
    __shared__ float xs[64][68];   // 68 pad: keeps 16B alignment (68*4=272=17*16)
    __shared__ float ws[64][64];

    const float* W;
    const float* b;
    float* out;
    if (blockIdx.y == 0)      { W = Wq; b = bq; out = g_q; }
    else if (blockIdx.y == 1) { W = Wk; b = bk; out = g_k; }
    else                      { W = Wv; b = bv; out = g_v; }

    const int r0  = blockIdx.x * 64;
    const int tid = threadIdx.x;

    // Load W tile (4096 f) and x tile (4096 f): 4 float4 each per thread.
    #pragma unroll
    for (int t = 0; t < 4; t++) {
        int i4  = tid + 256 * t;          // 0..1023 (float4 index)
        int row = i4 >> 4;
        int c4  = (i4 & 15) << 2;
        float4 wv4 = *(const float4*)(W + row * 64 + c4);
        *(float4*)(&ws[row][c4]) = wv4;
        int gr = r0 + row;
        float4 xv4 = (gr < N) ? *(const float4*)(x + (long long)gr * 64 + c4)
                              : make_float4(0.f, 0.f, 0.f, 0.f);
        *(float4*)(&xs[row][c4]) = xv4;
    }
    __syncthreads();

    const int tx = tid & 15;   // col group (4 cols)
    const int ty = tid >> 4;   // row group (4 rows)

    float4 bias4 = *(const float4*)(b + tx * 4);
    float acc[4][4];
    #pragma unroll
    for (int r = 0; r < 4; r++) {
        acc[r][0] = bias4.x; acc[r][1] = bias4.y;
        acc[r][2] = bias4.z; acc[r][3] = bias4.w;
    }

    #pragma unroll 8
    for (int k = 0; k < 64; k++) {
        float4 w4 = *(const float4*)(&ws[k][tx * 4]);
        float a0 = xs[ty * 4 + 0][k];
        float a1 = xs[ty * 4 + 1][k];
        float a2 = xs[ty * 4 + 2][k];
        float a3 = xs[ty * 4 + 3][k];
        acc[0][0] = fmaf(a0, w4.x, acc[0][0]); acc[0][1] = fmaf(a0, w4.y, acc[0][1]);
        acc[0][2] = fmaf(a0, w4.z, acc[0][2]); acc[0][3] = fmaf(a0, w4.w, acc[0][3]);
        acc[1][0] = fmaf(a1, w4.x, acc[1][0]); acc[1][1] = fmaf(a1, w4.y, acc[1][1]);
        acc[1][2] = fmaf(a1, w4.z, acc[1][2]); acc[1][3] = fmaf(a1, w4.w, acc[1][3]);
        acc[2][0] = fmaf(a2, w4.x, acc[2][0]); acc[2][1] = fmaf(a2, w4.y, acc[2][1]);
        acc[2][2] = fmaf(a2, w4.z, acc[2][2]); acc[2][3] = fmaf(a2, w4.w, acc[2][3]);
        acc[3][0] = fmaf(a3, w4.x, acc[3][0]); acc[3][1] = fmaf(a3, w4.y, acc[3][1]);
        acc[3][2] = fmaf(a3, w4.z, acc[3][2]); acc[3][3] = fmaf(a3, w4.w, acc[3][3]);
    }

    #pragma unroll
    for (int r = 0; r < 4; r++) {
        int gr = r0 + ty * 4 + r;
        if (gr < N) {
            float4 o4 = make_float4(acc[r][0], acc[r][1], acc[r][2], acc[r][3]);
            *(float4*)(out + (long long)gr * 64 + tx * 4) = o4;
        }
    }
}

// ---------------------------------------------------------------------------
// Kernel 2: per-point attention. grid = N blocks, 128 threads.
// Thread (j = tid>>3, l = tid&7) owns neighbor j, channels [l*8, l*8+8).
// ---------------------------------------------------------------------------
__global__ void __launch_bounds__(128) pt_attn(
    const float* __restrict__ p,
    const int*   __restrict__ idx,
    const float* __restrict__ Wp1, const float* __restrict__ bp1,
    const float* __restrict__ gp,  const float* __restrict__ bpv,
    const float* __restrict__ Wp2, const float* __restrict__ bp2,
    const float* __restrict__ g1,  const float* __restrict__ bb1,
    const float* __restrict__ Wa,  const float* __restrict__ ba,
    const float* __restrict__ g2,  const float* __restrict__ bb2,
    const float* __restrict__ Wb,  const float* __restrict__ bw,
    float* __restrict__ out, int N)
{
    const int i   = blockIdx.x;
    const int tid = threadIdx.x;
    const int j   = tid >> 3;
    const int l   = tid & 7;

    __shared__ float s_q[64];
    __shared__ float s_val[NS][68];     // v_gather + pe (padded: 2-way worst conflicts)
    __shared__ float s_wraw[NS][8];
    __shared__ float s_w[NS][8];
    __shared__ float s_Wa[64][9];       // padded
    __shared__ float s_Wp2[3][64];
    __shared__ float s_bp2[64];
    __shared__ float s_s1[64];
    __shared__ float s_b1[64];
    __shared__ float s_Wb[8][8];
    __shared__ float s_misc[32];        // [0:8)=ba, [8:16)=s2, [16:24)=b2, [24:32)=bw
    __shared__ float s_max[8];
    __shared__ float s_inv[8];

    const float bninv = rsqrtf(1.f + 1e-5f);

    // Stage weights/biases into smem.
    if (tid < 64) {
        s_q[tid]   = g_q[(long long)i * 64 + tid];
        s_bp2[tid] = __ldg(bp2 + tid);
        s_s1[tid]  = __ldg(g1 + tid) * bninv;
        s_b1[tid]  = __ldg(bb1 + tid);
    } else {
        int t = tid - 64;               // 0..63
        s_Wb[t >> 3][t & 7] = __ldg(Wb + t);
    }
    for (int t = tid; t < 512; t += 128) s_Wa[t >> 3][t & 7] = __ldg(Wa + t);
    for (int t = tid; t < 192; t += 128) s_Wp2[t / 64][t % 64] = __ldg(Wp2 + t);
    if (tid < 8) {
        s_misc[tid]      = __ldg(ba + tid);
        s_misc[8 + tid]  = __ldg(g2 + tid) * bninv;
        s_misc[16 + tid] = __ldg(bb2 + tid);
        s_misc[24 + tid] = __ldg(bw + tid);
    }
    __syncthreads();

    // Relative position & positional-MLP hidden (redundant per 8 lanes, cheap).
    const float pi0 = __ldg(p + (long long)i * 3 + 0);
    const float pi1 = __ldg(p + (long long)i * 3 + 1);
    const float pi2 = __ldg(p + (long long)i * 3 + 2);
    const int   nj  = __ldg(idx + (long long)i * NS + j);
    const float r0  = __ldg(p + (long long)nj * 3 + 0) - pi0;
    const float r1  = __ldg(p + (long long)nj * 3 + 1) - pi1;
    const float r2  = __ldg(p + (long long)nj * 3 + 2) - pi2;

    float t3[3];
    #pragma unroll
    for (int o = 0; o < 3; o++) {
        float u = r0 * __ldg(Wp1 + o) + r1 * __ldg(Wp1 + 3 + o) + r2 * __ldg(Wp1 + 6 + o)
                + __ldg(bp1 + o);
        u = u * (__ldg(gp + o) * bninv) + __ldg(bpv + o);
        t3[o] = fmaxf(u, 0.f);
    }

    // Gather K and V rows (contiguous float4s across l).
    const float4* kp = (const float4*)(g_k + (long long)nj * 64 + l * 8);
    const float4* vp = (const float4*)(g_v + (long long)nj * 64 + l * 8);
    float4 k0 = kp[0], k1 = kp[1];
    float4 v0 = vp[0], v1 = vp[1];
    float kk[8] = {k0.x, k0.y, k0.z, k0.w, k1.x, k1.y, k1.z, k1.w};
    float vv[8] = {v0.x, v0.y, v0.z, v0.w, v1.x, v1.y, v1.z, v1.w};

    float acc[8];
    #pragma unroll
    for (int ch = 0; ch < 8; ch++) acc[ch] = 0.f;

    #pragma unroll
    for (int m = 0; m < 8; m++) {
        int c = l * 8 + m;
        float pe = fmaf(t3[0], s_Wp2[0][c],
                   fmaf(t3[1], s_Wp2[1][c],
                   fmaf(t3[2], s_Wp2[2][c], s_bp2[c])));
        s_val[j][c] = vv[m] + pe;
        float wvv = kk[m] - s_q[c] + pe;
        wvv = fmaxf(fmaf(wvv, s_s1[c], s_b1[c]), 0.f);
        #pragma unroll
        for (int ch = 0; ch < 8; ch++)
            acc[ch] = fmaf(wvv, s_Wa[c][ch], acc[ch]);
    }

    // Reduce across the 8 lanes owning this neighbor (xor stays in j-group).
    #pragma unroll
    for (int off = 1; off < 8; off <<= 1) {
        #pragma unroll
        for (int ch = 0; ch < 8; ch++)
            acc[ch] += __shfl_xor_sync(0xffffffffu, acc[ch], off);
    }

    // BN2 + ReLU + Wb; each lane emits score channel l.
    float sc = s_misc[24 + l];   // bw[l]
    #pragma unroll
    for (int ch = 0; ch < 8; ch++) {
        float a = fmaxf(fmaf(acc[ch] + s_misc[ch], s_misc[8 + ch], s_misc[16 + ch]), 0.f);
        // note: _bn is (x)*s2 + b2 applied AFTER adding ba: (acc+ba)*s2+b2
        sc = fmaf(a, s_Wb[ch][l], sc);
    }
    s_wraw[j][l] = sc;
    __syncthreads();

    // Softmax over the 16 neighbors, per channel.
    if (tid < 8) {
        float mx = -1e30f;
        #pragma unroll
        for (int jj = 0; jj < NS; jj++) mx = fmaxf(mx, s_wraw[jj][tid]);
        float sm = 0.f;
        #pragma unroll
        for (int jj = 0; jj < NS; jj++) sm += expf(s_wraw[jj][tid] - mx);
        s_max[tid] = mx;
        s_inv[tid] = 1.f / sm;
    }
    __syncthreads();
    s_w[j][l] = expf(s_wraw[j][l] - s_max[l]) * s_inv[l];
    __syncthreads();

    // Aggregate: out[c] = sum_j val[j][c] * w[j][c & 7]
    if (tid < 64) {
        float o = 0.f;
        #pragma unroll
        for (int jj = 0; jj < NS; jj++)
            o = fmaf(s_val[jj][tid], s_w[jj][tid & 7], o);
        out[(long long)i * 64 + tid] = o;
    }
}

// ---------------------------------------------------------------------------
extern "C" void kernel_launch(void* const* d_in, const int* in_sizes, int n_in,
                              void* d_out, int out_size)
{
    const float* p   = (const float*)d_in[0];
    const float* x   = (const float*)d_in[1];
    const int*   idx = (const int*)  d_in[2];
    const float* Wq  = (const float*)d_in[3];
    const float* bq  = (const float*)d_in[4];
    const float* Wk  = (const float*)d_in[5];
    const float* bk  = (const float*)d_in[6];
    const float* Wv  = (const float*)d_in[7];
    const float* bv  = (const float*)d_in[8];
    const float* Wp1 = (const float*)d_in[9];
    const float* bp1 = (const float*)d_in[10];
    const float* gp  = (const float*)d_in[11];
    const float* bpv = (const float*)d_in[12];
    const float* Wp2 = (const float*)d_in[13];
    const float* bp2 = (const float*)d_in[14];
    const float* g1  = (const float*)d_in[15];
    const float* bb1 = (const float*)d_in[16];
    const float* Wa  = (const float*)d_in[17];
    const float* ba  = (const float*)d_in[18];
    const float* g2  = (const float*)d_in[19];
    const float* bb2 = (const float*)d_in[20];
    const float* Wb  = (const float*)d_in[21];
    const float* bw  = (const float*)d_in[22];
    float* out = (float*)d_out;

    int N = in_sizes[1] / C;
    if (N > MAXN) N = MAXN;

    dim3 gridA((N + 63) / 64, 3);
    qkv_gemm<<<gridA, 256>>>(x, Wq, bq, Wk, bk, Wv, bv, N);

    pt_attn<<<N, 128>>>(p, idx, Wp1, bp1, gp, bpv, Wp2, bp2,
                        g1, bb1, Wa, ba, g2, bb2, Wb, bw, out, N);
}

// round 2
// speedup vs baseline: 1.5252x; 1.5252x over previous
#include <cuda_runtime.h>
#include <math.h>

#define MAXN 100000
#define NS 16
#define C 64
#define PTS 8          // points per block (sequential)

// Scratch for Q/K/V projections (allocation-free rule: __device__ globals)
__device__ float g_q[MAXN * C];
__device__ float g_k[MAXN * C];
__device__ float g_v[MAXN * C];

// ---------------------------------------------------------------------------
// Kernel 1: QKV projection. grid = (ceil(N/64), 3). 256 threads.
// ---------------------------------------------------------------------------
__global__ void __launch_bounds__(256) qkv_gemm(
    const float* __restrict__ x,
    const float* __restrict__ Wq, const float* __restrict__ bq,
    const float* __restrict__ Wk, const float* __restrict__ bk,
    const float* __restrict__ Wv, const float* __restrict__ bv,
    int N)
{
    __shared__ float xs[64][68];
    __shared__ float ws[64][64];

    const float* W;
    const float* b;
    float* out;
    if (blockIdx.y == 0)      { W = Wq; b = bq; out = g_q; }
    else if (blockIdx.y == 1) { W = Wk; b = bk; out = g_k; }
    else                      { W = Wv; b = bv; out = g_v; }

    const int r0  = blockIdx.x * 64;
    const int tid = threadIdx.x;

    #pragma unroll
    for (int t = 0; t < 4; t++) {
        int i4  = tid + 256 * t;
        int row = i4 >> 4;
        int c4  = (i4 & 15) << 2;
        float4 wv4 = *(const float4*)(W + row * 64 + c4);
        *(float4*)(&ws[row][c4]) = wv4;
        int gr = r0 + row;
        float4 xv4 = (gr < N) ? *(const float4*)(x + (long long)gr * 64 + c4)
                              : make_float4(0.f, 0.f, 0.f, 0.f);
        *(float4*)(&xs[row][c4]) = xv4;
    }
    __syncthreads();

    const int tx = tid & 15;
    const int ty = tid >> 4;

    float4 bias4 = *(const float4*)(b + tx * 4);
    float acc[4][4];
    #pragma unroll
    for (int r = 0; r < 4; r++) {
        acc[r][0] = bias4.x; acc[r][1] = bias4.y;
        acc[r][2] = bias4.z; acc[r][3] = bias4.w;
    }

    #pragma unroll 8
    for (int k = 0; k < 64; k++) {
        float4 w4 = *(const float4*)(&ws[k][tx * 4]);
        float a0 = xs[ty * 4 + 0][k];
        float a1 = xs[ty * 4 + 1][k];
        float a2 = xs[ty * 4 + 2][k];
        float a3 = xs[ty * 4 + 3][k];
        acc[0][0] = fmaf(a0, w4.x, acc[0][0]); acc[0][1] = fmaf(a0, w4.y, acc[0][1]);
        acc[0][2] = fmaf(a0, w4.z, acc[0][2]); acc[0][3] = fmaf(a0, w4.w, acc[0][3]);
        acc[1][0] = fmaf(a1, w4.x, acc[1][0]); acc[1][1] = fmaf(a1, w4.y, acc[1][1]);
        acc[1][2] = fmaf(a1, w4.z, acc[1][2]); acc[1][3] = fmaf(a1, w4.w, acc[1][3]);
        acc[2][0] = fmaf(a2, w4.x, acc[2][0]); acc[2][1] = fmaf(a2, w4.y, acc[2][1]);
        acc[2][2] = fmaf(a2, w4.z, acc[2][2]); acc[2][3] = fmaf(a2, w4.w, acc[2][3]);
        acc[3][0] = fmaf(a3, w4.x, acc[3][0]); acc[3][1] = fmaf(a3, w4.y, acc[3][1]);
        acc[3][2] = fmaf(a3, w4.z, acc[3][2]); acc[3][3] = fmaf(a3, w4.w, acc[3][3]);
    }

    #pragma unroll
    for (int r = 0; r < 4; r++) {
        int gr = r0 + ty * 4 + r;
        if (gr < N) {
            float4 o4 = make_float4(acc[r][0], acc[r][1], acc[r][2], acc[r][3]);
            *(float4*)(out + (long long)gr * 64 + tx * 4) = o4;
        }
    }
}

// ---------------------------------------------------------------------------
// Kernel 2: per-point attention. Block = 128 threads handles PTS points
// sequentially. Thread (j = tid>>3, l = tid&7): neighbor j, channels
// {h*32 + l*4 + m : h<2, m<4} in phase A; score channel l in phase B.
// ---------------------------------------------------------------------------
__global__ void __launch_bounds__(128) pt_attn(
    const float* __restrict__ p,
    const int*   __restrict__ idx,
    const float* __restrict__ Wp1, const float* __restrict__ bp1,
    const float* __restrict__ gp,  const float* __restrict__ bpv,
    const float* __restrict__ Wp2, const float* __restrict__ bp2,
    const float* __restrict__ g1,  const float* __restrict__ bb1,
    const float* __restrict__ Wa,  const float* __restrict__ ba,
    const float* __restrict__ g2,  const float* __restrict__ bb2,
    const float* __restrict__ Wb,  const float* __restrict__ bw,
    float* __restrict__ out, int N)
{
    const int tid = threadIdx.x;
    const int j   = tid >> 3;
    const int l   = tid & 7;

    // block-constant staged weights
    __shared__ float s_Wat[8][68];     // Wa^T: [ch][c]
    __shared__ float s_Wbt[8][12];     // Wb^T: [lout][ch]
    __shared__ float s_s1[64], s_b1[64], s_bp2[64];
    __shared__ float s_Wp2[3][64];
    __shared__ float s_misc[64];       // 0:ba 8:s2 16:b2 24:bw 32:Wp1(9) 41:bp1 44:gp*inv 47:bp
    // per-point
    __shared__ float s_wv[NS][72];
    __shared__ float s_val[NS][72];
    __shared__ float s_a[NS][12];
    __shared__ float s_wraw[NS][12];
    __shared__ float s_w[NS][12];
    __shared__ float s_mx[8], s_inv[8];

    const float bninv = rsqrtf(1.f + 1e-5f);

    // ---- stage weights once per block ----
    for (int t = tid; t < 512; t += 128) s_Wat[t & 7][t >> 3] = __ldg(Wa + t);
    if (tid < 64) {
        s_Wbt[tid & 7][tid >> 3] = __ldg(Wb + tid);
        s_s1[tid]  = __ldg(g1 + tid) * bninv;
        s_b1[tid]  = __ldg(bb1 + tid);
        s_bp2[tid] = __ldg(bp2 + tid);
    }
    for (int t = tid; t < 192; t += 128) s_Wp2[t / 64][t % 64] = __ldg(Wp2 + t);
    if (tid < 8) {
        s_misc[tid]      = __ldg(ba + tid);
        s_misc[8 + tid]  = __ldg(g2 + tid) * bninv;
        s_misc[16 + tid] = __ldg(bb2 + tid);
        s_misc[24 + tid] = __ldg(bw + tid);
    }
    if (tid < 9)  s_misc[32 + tid] = __ldg(Wp1 + tid);
    if (tid < 3) {
        s_misc[41 + tid] = __ldg(bp1 + tid);
        s_misc[44 + tid] = __ldg(gp + tid) * bninv;
        s_misc[47 + tid] = __ldg(bpv + tid);
    }
    __syncthreads();

    const int i0 = blockIdx.x * PTS;

    #pragma unroll 1
    for (int it = 0; it < PTS; it++) {
        const int i = i0 + it;
        const bool act = (i < N);     // uniform across block

        if (act) {
            // ---- Phase A: pe, wv, val ----
            const int nj = __ldg(idx + i * NS + j);
            const float r0 = __ldg(p + nj * 3 + 0) - __ldg(p + i * 3 + 0);
            const float r1 = __ldg(p + nj * 3 + 1) - __ldg(p + i * 3 + 1);
            const float r2 = __ldg(p + nj * 3 + 2) - __ldg(p + i * 3 + 2);
            float t3[3];
            #pragma unroll
            for (int o = 0; o < 3; o++) {
                float u = fmaf(r0, s_misc[32 + o],
                          fmaf(r1, s_misc[35 + o],
                          fmaf(r2, s_misc[38 + o], s_misc[41 + o])));
                t3[o] = fmaxf(fmaf(u, s_misc[44 + o], s_misc[47 + o]), 0.f);
            }

            #pragma unroll
            for (int h = 0; h < 2; h++) {
                const int c0 = h * 32 + l * 4;
                float4 q4 = *(const float4*)(g_q + (long long)i  * 64 + c0);
                float4 k4 = *(const float4*)(g_k + (long long)nj * 64 + c0);
                float4 v4 = *(const float4*)(g_v + (long long)nj * 64 + c0);
                float4 s1 = *(const float4*)&s_s1[c0];
                float4 b1 = *(const float4*)&s_b1[c0];
                float4 b2 = *(const float4*)&s_bp2[c0];
                float4 w0 = *(const float4*)&s_Wp2[0][c0];
                float4 w1 = *(const float4*)&s_Wp2[1][c0];
                float4 w2 = *(const float4*)&s_Wp2[2][c0];

                float4 pe, val, wv;
                pe.x = fmaf(t3[0], w0.x, fmaf(t3[1], w1.x, fmaf(t3[2], w2.x, b2.x)));
                pe.y = fmaf(t3[0], w0.y, fmaf(t3[1], w1.y, fmaf(t3[2], w2.y, b2.y)));
                pe.z = fmaf(t3[0], w0.z, fmaf(t3[1], w1.z, fmaf(t3[2], w2.z, b2.z)));
                pe.w = fmaf(t3[0], w0.w, fmaf(t3[1], w1.w, fmaf(t3[2], w2.w, b2.w)));
                val.x = v4.x + pe.x; val.y = v4.y + pe.y;
                val.z = v4.z + pe.z; val.w = v4.w + pe.w;
                wv.x = fmaxf(fmaf(k4.x - q4.x + pe.x, s1.x, b1.x), 0.f);
                wv.y = fmaxf(fmaf(k4.y - q4.y + pe.y, s1.y, b1.y), 0.f);
                wv.z = fmaxf(fmaf(k4.z - q4.z + pe.z, s1.z, b1.z), 0.f);
                wv.w = fmaxf(fmaf(k4.w - q4.w + pe.w, s1.w, b1.w), 0.f);
                *(float4*)&s_val[j][c0] = val;
                *(float4*)&s_wv[j][c0]  = wv;
            }
        }
        __syncwarp();

        if (act) {
            // ---- Phase B: y[j][ch=l] = sum_c wv[j][c] * Wa[c][l] ----
            float y = 0.f;
            #pragma unroll
            for (int c4 = 0; c4 < 16; c4++) {
                float4 a4 = *(const float4*)&s_wv[j][c4 * 4];
                float4 w4 = *(const float4*)&s_Wat[l][c4 * 4];
                y = fmaf(a4.x, w4.x, y); y = fmaf(a4.y, w4.y, y);
                y = fmaf(a4.z, w4.z, y); y = fmaf(a4.w, w4.w, y);
            }
            float a = fmaxf(fmaf(y + s_misc[l], s_misc[8 + l], s_misc[16 + l]), 0.f);
            s_a[j][l] = a;
        }
        __syncwarp();

        if (act) {
            // ---- score[j][l] = bw[l] + sum_ch a[j][ch] * Wb[ch][l] ----
            float4 a0 = *(const float4*)&s_a[j][0];
            float4 a1 = *(const float4*)&s_a[j][4];
            float4 w0 = *(const float4*)&s_Wbt[l][0];
            float4 w1 = *(const float4*)&s_Wbt[l][4];
            float sc = s_misc[24 + l];
            sc = fmaf(a0.x, w0.x, sc); sc = fmaf(a0.y, w0.y, sc);
            sc = fmaf(a0.z, w0.z, sc); sc = fmaf(a0.w, w0.w, sc);
            sc = fmaf(a1.x, w1.x, sc); sc = fmaf(a1.y, w1.y, sc);
            sc = fmaf(a1.z, w1.z, sc); sc = fmaf(a1.w, w1.w, sc);
            s_wraw[j][l] = sc;
        }
        __syncthreads();

        // ---- softmax over neighbors, per score channel (8 threads) ----
        if (act && tid < 8) {
            float mx = -1e30f;
            #pragma unroll
            for (int jj = 0; jj < NS; jj++) mx = fmaxf(mx, s_wraw[jj][tid]);
            float sm = 0.f;
            #pragma unroll
            for (int jj = 0; jj < NS; jj++) sm += __expf(s_wraw[jj][tid] - mx);
            float inv = 1.f / sm;
            #pragma unroll
            for (int jj = 0; jj < NS; jj++)
                s_w[jj][tid] = __expf(s_wraw[jj][tid] - mx) * inv;
        }
        __syncthreads();

        // ---- aggregation: 16 threads, float4 over channels ----
        if (act && tid < 16) {
            const int cb  = tid * 4;
            const int wb4 = (tid & 1) * 4;
            float4 o = make_float4(0.f, 0.f, 0.f, 0.f);
            #pragma unroll
            for (int jj = 0; jj < NS; jj++) {
                float4 v4 = *(const float4*)&s_val[jj][cb];
                float4 w4 = *(const float4*)&s_w[jj][wb4];
                o.x = fmaf(v4.x, w4.x, o.x); o.y = fmaf(v4.y, w4.y, o.y);
                o.z = fmaf(v4.z, w4.z, o.z); o.w = fmaf(v4.w, w4.w, o.w);
            }
            *(float4*)(out + (long long)i * 64 + cb) = o;
        }
        __syncthreads();
    }
}

// ---------------------------------------------------------------------------
extern "C" void kernel_launch(void* const* d_in, const int* in_sizes, int n_in,
                              void* d_out, int out_size)
{
    const float* p   = (const float*)d_in[0];
    const float* x   = (const float*)d_in[1];
    const int*   idx = (const int*)  d_in[2];
    const float* Wq  = (const float*)d_in[3];
    const float* bq  = (const float*)d_in[4];
    const float* Wk  = (const float*)d_in[5];
    const float* bk  = (const float*)d_in[6];
    const float* Wv  = (const float*)d_in[7];
    const float* bv  = (const float*)d_in[8];
    const float* Wp1 = (const float*)d_in[9];
    const float* bp1 = (const float*)d_in[10];
    const float* gp  = (const float*)d_in[11];
    const float* bpv = (const float*)d_in[12];
    const float* Wp2 = (const float*)d_in[13];
    const float* bp2 = (const float*)d_in[14];
    const float* g1  = (const float*)d_in[15];
    const float* bb1 = (const float*)d_in[16];
    const float* Wa  = (const float*)d_in[17];
    const float* ba  = (const float*)d_in[18];
    const float* g2  = (const float*)d_in[19];
    const float* bb2 = (const float*)d_in[20];
    const float* Wb  = (const float*)d_in[21];
    const float* bw  = (const float*)d_in[22];
    float* out = (float*)d_out;

    int N = in_sizes[1] / C;
    if (N > MAXN) N = MAXN;

    dim3 gridA((N + 63) / 64, 3);
    qkv_gemm<<<gridA, 256>>>(x, Wq, bq, Wk, bk, Wv, bv, N);

    pt_attn<<<(N + PTS - 1) / PTS, 128>>>(p, idx, Wp1, bp1, gp, bpv, Wp2, bp2,
                                          g1, bb1, Wa, ba, g2, bb2, Wb, bw, out, N);
}